// round 16
// baseline (speedup 1.0000x reference)
#include <cuda_runtime.h>
#include <cuda_fp16.h>
#include <mma.h>
#include <math.h>
#include <stdint.h>

using namespace nvcuda;

#define TT 256      // timesteps
#define BB 256      // batch
#define DD 1024     // hidden dim
#define WS 2048     // W row stride (W is (D, 2D) row-major)

// fp16 shadow of the hidden state, written each step; A-operand source.
__device__ __align__(16) __half g_h[BB * DD];   // 512 KB

// ===========================================================================
// Kernel 1: preactivations, fp16 wmma (fp32 accum), 128x128 tile.  (R13)
//   out[(b*TT + t)*DD + d] = bias[d] + sum_k x[(t*BB+b)*DD + k] * W[d*WS + k]
// ===========================================================================
#define X_BM 128
#define X_BN 128
#define X_BK 32
#define X_LDH 40                          // smem ldm in halfs (80B rows)
#define X_TILEH (X_BM * X_LDH)            // 5120 halfs = 10240 B
#define X_SMEM_BYTES 65536                // max(4 tiles = 40960, sC = 65536)

__global__ void __launch_bounds__(256)
gemm_x_f16(const float* __restrict__ x, const float* __restrict__ W,
           const float* __restrict__ bias, float* __restrict__ out)
{
    extern __shared__ char smraw[];
    __half* sA[2] = { (__half*)smraw,                 (__half*)(smraw + 2 * X_TILEH * 2) };
    __half* sB[2] = { (__half*)(smraw + X_TILEH * 2), (__half*)(smraw + 3 * X_TILEH * 2) };

    const int r0  = blockIdx.y * X_BM;    // row tile in (t*BB + b) space
    const int d0  = blockIdx.x * X_BN;
    const int tid = threadIdx.x;
    const int wid = tid >> 5;
    const int warpM = wid & 3;            // 4 x 32 rows
    const int warpN = wid >> 2;           // 2 x 64 cols

    wmma::fragment<wmma::accumulator, 16, 16, 16, float> acc[2][4];
    #pragma unroll
    for (int mi = 0; mi < 2; ++mi)
        #pragma unroll
        for (int ni = 0; ni < 4; ++ni)
            wmma::fill_fragment(acc[mi][ni], 0.0f);

    auto load_chunk = [&](int k0, __half* dA, __half* dB) {
        #pragma unroll
        for (int j = 0; j < 4; ++j) {
            int f   = tid + j * 256;      // 1024 float4
            int row = f >> 3;             // 8 float4 per row (32 floats)
            int c4  = f & 7;
            float4 va = *reinterpret_cast<const float4*>(
                &x[(size_t)(r0 + row) * DD + k0 + c4 * 4]);
            __half2* pa = reinterpret_cast<__half2*>(&dA[row * X_LDH + c4 * 4]);
            pa[0] = __floats2half2_rn(va.x, va.y);
            pa[1] = __floats2half2_rn(va.z, va.w);
            float4 vb = *reinterpret_cast<const float4*>(
                &W[(size_t)(d0 + row) * WS + k0 + c4 * 4]);
            __half2* pb = reinterpret_cast<__half2*>(&dB[row * X_LDH + c4 * 4]);
            pb[0] = __floats2half2_rn(vb.x, vb.y);
            pb[1] = __floats2half2_rn(vb.z, vb.w);
        }
    };

    load_chunk(0, sA[0], sB[0]);
    __syncthreads();

    const int NCH = DD / X_BK;            // 32 chunks
    for (int c = 0; c < NCH; ++c) {
        int cur = c & 1;
        if (c + 1 < NCH) load_chunk((c + 1) * X_BK, sA[cur ^ 1], sB[cur ^ 1]);

        #pragma unroll
        for (int kk = 0; kk < X_BK; kk += 16) {
            wmma::fragment<wmma::matrix_a, 16, 16, 16, __half, wmma::row_major> a[2];
            #pragma unroll
            for (int mi = 0; mi < 2; ++mi)
                wmma::load_matrix_sync(a[mi], &sA[cur][(warpM * 32 + mi * 16) * X_LDH + kk], X_LDH);
            #pragma unroll
            for (int ni = 0; ni < 4; ++ni) {
                wmma::fragment<wmma::matrix_b, 16, 16, 16, __half, wmma::col_major> b;
                wmma::load_matrix_sync(b, &sB[cur][(warpN * 64 + ni * 16) * X_LDH + kk], X_LDH);
                #pragma unroll
                for (int mi = 0; mi < 2; ++mi)
                    wmma::mma_sync(acc[mi][ni], a[mi], b, acc[mi][ni]);
            }
        }
        __syncthreads();
    }

    // Stage C (fp32) in smem, overlaying the fp16 tiles
    float* sC = (float*)smraw;
    #pragma unroll
    for (int mi = 0; mi < 2; ++mi)
        #pragma unroll
        for (int ni = 0; ni < 4; ++ni)
            wmma::store_matrix_sync(&sC[(warpM * 32 + mi * 16) * X_BN + warpN * 64 + ni * 16],
                                    acc[mi][ni], X_BN, wmma::mem_row_major);
    __syncthreads();

    // Epilogue: +bias, scatter. Block spans 128 rows => t constant.
    const int t = r0 >> 8;
    const int bbase = r0 & 255;
    #pragma unroll
    for (int j = 0; j < 16; ++j) {
        int f   = tid + j * 256;          // 4096 float4
        int row = f >> 5;                 // 32 float4 per row
        int c4  = f & 31;
        float4 bv = *reinterpret_cast<const float4*>(&bias[d0 + c4 * 4]);
        const float* cp = &sC[row * X_BN + c4 * 4];
        float4 o;
        o.x = cp[0] + bv.x; o.y = cp[1] + bv.y; o.z = cp[2] + bv.z; o.w = cp[3] + bv.w;
        *reinterpret_cast<float4*>(
            &out[((size_t)((bbase + row) * TT + t)) * DD + d0 + c4 * 4]) = o;
    }
}

// ===========================================================================
// Kernel 2: persistent recurrence, fp16 operands, fp32 accum.
//   - 128 blocks x 512 threads; block tile = 32 batch x 64 d.
//   - Wh stripe (64 x 1024 fp16, 132 KB) resident in smem for all steps.
//   - FULL h tile (32 x 1024 fp16, 66 KB) per step via cp.async (2 halves).
//   - NEW: 16 warps = 2(N-half) x 8(K-split of 128); warp tile 32x32 with
//     4 accumulators -> 1 mma per fragment load (2x less smem frag traffic).
//     8 K-partials stored into the (then-dead) A region; epilogue sums them.
//   - 8 independent batch groups of 16 blocks; acq/rel barrier.
// ===========================================================================
#define RH_BM 32
#define RH_BN 64
#define RH_WLDH 1032                      // Wh ldm in halfs (1024+8)
#define RH_ALDH 1032                      // h  ldm in halfs (1024+8)
#define RH_GRPBLK 16                      // blocks per barrier group

#define RH_WH_BYTES (RH_BN * RH_WLDH * 2)             // 132096
#define RH_A_BYTES  (RH_BM * RH_ALDH * 2)             // 66048
#define RH_OFF_A  RH_WH_BYTES                         // 132096
#define RH_SMEM_BYTES (RH_OFF_A + RH_A_BYTES)         // 198144
// partial-C region overlays A (16 tiles of 32x32 fp32 = 65536 <= 66048)

__device__ __align__(256) unsigned g_cnt[8 * 64];
__device__ __align__(256) unsigned g_phase[8 * 64];   // monotonic across replays

__device__ __forceinline__ unsigned bar_arrive_acqrel(unsigned* p) {
    unsigned old;
    asm volatile("atom.acq_rel.gpu.add.u32 %0,[%1],1;"
                 : "=r"(old) : "l"(p) : "memory");
    return old;
}
__device__ __forceinline__ void bar_reset_relaxed(unsigned* p) {
    asm volatile("st.relaxed.gpu.u32 [%0],0;" :: "l"(p) : "memory");
}
__device__ __forceinline__ void bar_release(unsigned* p) {
    asm volatile("red.release.gpu.add.u32 [%0],1;" :: "l"(p) : "memory");
}
__device__ __forceinline__ unsigned bar_poll_acquire(const unsigned* p) {
    unsigned v;
    asm volatile("ld.acquire.gpu.u32 %0,[%1];" : "=r"(v) : "l"(p) : "memory");
    return v;
}
__device__ __forceinline__ void cp16(uint32_t saddr, const void* gptr) {
    asm volatile("cp.async.cg.shared.global [%0], [%1], 16;"
                 :: "r"(saddr), "l"(gptr));
}

__global__ void __launch_bounds__(512)
rnn_persistent(const float* __restrict__ W, float* __restrict__ out)
{
    extern __shared__ char smraw[];
    __half* sWh = (__half*)smraw;
    __half* sA  = (__half*)(smraw + RH_OFF_A);
    float*  sP  = (float*)(smraw + RH_OFF_A);   // partial-C overlay (post-mma)
    __shared__ unsigned s_base;

    const int tid = threadIdx.x;
    const int wid = tid >> 5;             // 16 warps = 2(N-half) x 8(K-split)
    const int npos = wid & 1;             // N half: cols [npos*32, npos*32+32)
    const int kIdx = wid >> 1;            // K slice: [kIdx*128, kIdx*128+128)

    const int nT = blockIdx.x & 15;       // 16 d-stripes of 64
    const int mT = blockIdx.x >> 4;       // 8 batch groups of 32 (barrier scope)
    const int d0 = nT * RH_BN;
    const int b0 = mT * RH_BM;

    unsigned* cntp   = &g_cnt[mT * 64];
    unsigned* phasep = &g_phase[mT * 64];

    const uint32_t sA_u32 = (uint32_t)__cvta_generic_to_shared(sA);

    // --- Load Wh stripe once (fp32 -> fp16 RN): sWh[d][k], d = 0..63 ---
    {
        const float* Wh = W + DD;
        #pragma unroll
        for (int j = 0; j < 32; ++j) {
            int f   = tid + j * 512;
            int row = f >> 8;
            int c4  = f & 255;
            float4 v = *reinterpret_cast<const float4*>(
                &Wh[(size_t)(d0 + row) * WS + c4 * 4]);
            __half2* p = reinterpret_cast<__half2*>(&sWh[row * RH_WLDH + c4 * 4]);
            p[0] = __floats2half2_rn(v.x, v.y);
            p[1] = __floats2half2_rn(v.z, v.w);
        }
    }

    if (tid == 0) s_base = bar_poll_acquire(phasep);
    __syncthreads();
    const unsigned base = s_base;

    // full h tile: 32 rows x 1024 halfs; half h covers k [h*512, h*512+512)
    auto issue_half = [&](int h) {
        #pragma unroll
        for (int j = 0; j < 4; ++j) {
            int f   = tid + j * 512;      // 2048 segs: 32 rows x 64 segs
            int row = f >> 6;
            int sg  = (f & 63) + h * 64;
            const void* g = &g_h[(size_t)(b0 + row) * DD + sg * 8];
            uint32_t s = sA_u32 + (uint32_t)(row * RH_ALDH + sg * 8) * 2u;
            cp16(s, g);
        }
        asm volatile("cp.async.commit_group;");
    };

    // epilogue map: 32x64 floats = 512 float4, 1 per thread
    const int erow = tid >> 4;            // 16 float4 per row
    const int ec4  = tid & 15;
    const int enp  = ec4 >> 3;            // which N half
    const int ecc  = (ec4 & 7) * 4;       // col within 32-wide tile

    for (int t = 0; t < TT; ++t) {
        if (t == 0) {
            float* p = &out[((size_t)((b0 + erow) * TT + 0)) * DD + d0 + ec4 * 4];
            float4 v = __ldcg(reinterpret_cast<const float4*>(p));
            v.x = tanhf(v.x); v.y = tanhf(v.y); v.z = tanhf(v.z); v.w = tanhf(v.w);
            *reinterpret_cast<float4*>(p) = v;
            union { uint2 u; __half2 h2[2]; } pk;
            pk.h2[0] = __floats2half2_rn(v.x, v.y);
            pk.h2[1] = __floats2half2_rn(v.z, v.w);
            __stcg(reinterpret_cast<uint2*>(
                &g_h[(size_t)(b0 + erow) * DD + d0 + ec4 * 4]), pk.u);
        } else {
            issue_half(0);
            issue_half(1);

            float* eptr = &out[((size_t)((b0 + erow) * TT + t)) * DD + d0 + ec4 * 4];
            float4 pre = __ldcg(reinterpret_cast<const float4*>(eptr));

            wmma::fragment<wmma::accumulator, 16, 16, 16, float> acc[2][2];
            #pragma unroll
            for (int mf = 0; mf < 2; ++mf)
                #pragma unroll
                for (int nf = 0; nf < 2; ++nf)
                    wmma::fill_fragment(acc[mf][nf], 0.0f);

            // 8 k-steps of 16 over this warp's 128-wide K slice
            auto do_ksteps = [&]() {
                const int kbase = kIdx * 128;
                #pragma unroll
                for (int s = 0; s < 8; ++s) {
                    const int k = kbase + s * 16;
                    wmma::fragment<wmma::matrix_a, 16, 16, 16, __half, wmma::row_major> a[2];
                    wmma::fragment<wmma::matrix_b, 16, 16, 16, __half, wmma::col_major> b[2];
                    wmma::load_matrix_sync(a[0], &sA[k], RH_ALDH);
                    wmma::load_matrix_sync(a[1], &sA[16 * RH_ALDH + k], RH_ALDH);
                    wmma::load_matrix_sync(b[0], &sWh[(npos * 32) * RH_WLDH + k], RH_WLDH);
                    wmma::load_matrix_sync(b[1], &sWh[(npos * 32 + 16) * RH_WLDH + k], RH_WLDH);
                    #pragma unroll
                    for (int mf = 0; mf < 2; ++mf)
                        #pragma unroll
                        for (int nf = 0; nf < 2; ++nf)
                            wmma::mma_sync(acc[mf][nf], a[mf], b[nf], acc[mf][nf]);
                }
            };

            // half 0 ready -> warps kIdx<4 compute while half 1 streams
            asm volatile("cp.async.wait_group 1;");
            __syncthreads();
            if (kIdx < 4) do_ksteps();
            asm volatile("cp.async.wait_group 0;");
            __syncthreads();
            if (kIdx >= 4) do_ksteps();
            __syncthreads();              // all mmas done; A region now dead

            // store this warp's 32x32 partial into its sP tile
            {
                float* tile = sP + (kIdx * 2 + npos) * 1024;
                wmma::store_matrix_sync(tile,            acc[0][0], 32, wmma::mem_row_major);
                wmma::store_matrix_sync(tile + 16,       acc[0][1], 32, wmma::mem_row_major);
                wmma::store_matrix_sync(tile + 16 * 32,  acc[1][0], 32, wmma::mem_row_major);
                wmma::store_matrix_sync(tile + 16 * 32 + 16, acc[1][1], 32, wmma::mem_row_major);
            }
            __syncthreads();

            // epilogue: sum 8 K-partials + preact -> tanh -> out + g_h
            {
                const int off = erow * 32 + ecc;
                float4 s0 = pre;
                #pragma unroll
                for (int kI = 0; kI < 8; ++kI) {
                    const float* pp = &sP[(kI * 2 + enp) * 1024 + off];
                    s0.x += pp[0]; s0.y += pp[1]; s0.z += pp[2]; s0.w += pp[3];
                }
                float4 o;
                o.x = tanhf(s0.x); o.y = tanhf(s0.y);
                o.z = tanhf(s0.z); o.w = tanhf(s0.w);
                *reinterpret_cast<float4*>(eptr) = o;
                union { uint2 u; __half2 h2[2]; } pk;
                pk.h2[0] = __floats2half2_rn(o.x, o.y);
                pk.h2[1] = __floats2half2_rn(o.z, o.w);
                __stcg(reinterpret_cast<uint2*>(
                    &g_h[(size_t)(b0 + erow) * DD + d0 + ec4 * 4]), pk.u);
            }
        }

        // group barrier (16 blocks sharing this batch group), skip after last
        if (t != TT - 1) {
            __syncthreads();
            if (tid == 0) {
                unsigned old = bar_arrive_acqrel(cntp);
                if (old == RH_GRPBLK - 1) {
                    bar_reset_relaxed(cntp);
                    bar_release(phasep);
                } else {
                    const unsigned target = base + (unsigned)(t + 1);
                    while ((int)(bar_poll_acquire(phasep) - target) < 0) { }
                }
            }
            __syncthreads();
        }
    }
}

// ===========================================================================
// Launch
// ===========================================================================
extern "C" void kernel_launch(void* const* d_in, const int* in_sizes, int n_in,
                              void* d_out, int out_size)
{
    const float* x    = (const float*)d_in[0];
    const float* W    = (const float*)d_in[1];
    const float* bias = (const float*)d_in[2];
    float* out = (float*)d_out;

    cudaFuncSetAttribute(gemm_x_f16, cudaFuncAttributeMaxDynamicSharedMemorySize,
                         X_SMEM_BYTES);
    cudaFuncSetAttribute(rnn_persistent, cudaFuncAttributeMaxDynamicSharedMemorySize,
                         RH_SMEM_BYTES);

    dim3 g1(DD / X_BN, (TT * BB) / X_BM);   // (8, 512)
    gemm_x_f16<<<g1, 256, X_SMEM_BYTES>>>(x, W, bias, out);

    rnn_persistent<<<128, 512, RH_SMEM_BYTES>>>(W, out);
}

// round 17
// speedup vs baseline: 1.0174x; 1.0174x over previous
#include <cuda_runtime.h>
#include <cuda_fp16.h>
#include <mma.h>
#include <math.h>
#include <stdint.h>

using namespace nvcuda;

#define TT 256      // timesteps
#define BB 256      // batch
#define DD 1024     // hidden dim
#define WS 2048     // W row stride (W is (D, 2D) row-major)

// fp16 shadow of the hidden state, written each step; A-operand source.
__device__ __align__(16) __half g_h[BB * DD];   // 512 KB

// ===========================================================================
// Kernel 1: preactivations, fp16 wmma (fp32 accum), 128x128 tile.  (R13)
//   out[(b*TT + t)*DD + d] = bias[d] + sum_k x[(t*BB+b)*DD + k] * W[d*WS + k]
// ===========================================================================
#define X_BM 128
#define X_BN 128
#define X_BK 32
#define X_LDH 40                          // smem ldm in halfs (80B rows)
#define X_TILEH (X_BM * X_LDH)            // 5120 halfs = 10240 B
#define X_SMEM_BYTES 65536                // max(4 tiles = 40960, sC = 65536)

__global__ void __launch_bounds__(256)
gemm_x_f16(const float* __restrict__ x, const float* __restrict__ W,
           const float* __restrict__ bias, float* __restrict__ out)
{
    extern __shared__ char smraw[];
    __half* sA[2] = { (__half*)smraw,                 (__half*)(smraw + 2 * X_TILEH * 2) };
    __half* sB[2] = { (__half*)(smraw + X_TILEH * 2), (__half*)(smraw + 3 * X_TILEH * 2) };

    const int r0  = blockIdx.y * X_BM;    // row tile in (t*BB + b) space
    const int d0  = blockIdx.x * X_BN;
    const int tid = threadIdx.x;
    const int wid = tid >> 5;
    const int warpM = wid & 3;            // 4 x 32 rows
    const int warpN = wid >> 2;           // 2 x 64 cols

    wmma::fragment<wmma::accumulator, 16, 16, 16, float> acc[2][4];
    #pragma unroll
    for (int mi = 0; mi < 2; ++mi)
        #pragma unroll
        for (int ni = 0; ni < 4; ++ni)
            wmma::fill_fragment(acc[mi][ni], 0.0f);

    auto load_chunk = [&](int k0, __half* dA, __half* dB) {
        #pragma unroll
        for (int j = 0; j < 4; ++j) {
            int f   = tid + j * 256;      // 1024 float4
            int row = f >> 3;             // 8 float4 per row (32 floats)
            int c4  = f & 7;
            float4 va = *reinterpret_cast<const float4*>(
                &x[(size_t)(r0 + row) * DD + k0 + c4 * 4]);
            __half2* pa = reinterpret_cast<__half2*>(&dA[row * X_LDH + c4 * 4]);
            pa[0] = __floats2half2_rn(va.x, va.y);
            pa[1] = __floats2half2_rn(va.z, va.w);
            float4 vb = *reinterpret_cast<const float4*>(
                &W[(size_t)(d0 + row) * WS + k0 + c4 * 4]);
            __half2* pb = reinterpret_cast<__half2*>(&dB[row * X_LDH + c4 * 4]);
            pb[0] = __floats2half2_rn(vb.x, vb.y);
            pb[1] = __floats2half2_rn(vb.z, vb.w);
        }
    };

    load_chunk(0, sA[0], sB[0]);
    __syncthreads();

    const int NCH = DD / X_BK;            // 32 chunks
    for (int c = 0; c < NCH; ++c) {
        int cur = c & 1;
        if (c + 1 < NCH) load_chunk((c + 1) * X_BK, sA[cur ^ 1], sB[cur ^ 1]);

        #pragma unroll
        for (int kk = 0; kk < X_BK; kk += 16) {
            wmma::fragment<wmma::matrix_a, 16, 16, 16, __half, wmma::row_major> a[2];
            #pragma unroll
            for (int mi = 0; mi < 2; ++mi)
                wmma::load_matrix_sync(a[mi], &sA[cur][(warpM * 32 + mi * 16) * X_LDH + kk], X_LDH);
            #pragma unroll
            for (int ni = 0; ni < 4; ++ni) {
                wmma::fragment<wmma::matrix_b, 16, 16, 16, __half, wmma::col_major> b;
                wmma::load_matrix_sync(b, &sB[cur][(warpN * 64 + ni * 16) * X_LDH + kk], X_LDH);
                #pragma unroll
                for (int mi = 0; mi < 2; ++mi)
                    wmma::mma_sync(acc[mi][ni], a[mi], b, acc[mi][ni]);
            }
        }
        __syncthreads();
    }

    // Stage C (fp32) in smem, overlaying the fp16 tiles
    float* sC = (float*)smraw;
    #pragma unroll
    for (int mi = 0; mi < 2; ++mi)
        #pragma unroll
        for (int ni = 0; ni < 4; ++ni)
            wmma::store_matrix_sync(&sC[(warpM * 32 + mi * 16) * X_BN + warpN * 64 + ni * 16],
                                    acc[mi][ni], X_BN, wmma::mem_row_major);
    __syncthreads();

    // Epilogue: +bias, scatter. Block spans 128 rows => t constant.
    const int t = r0 >> 8;
    const int bbase = r0 & 255;
    #pragma unroll
    for (int j = 0; j < 16; ++j) {
        int f   = tid + j * 256;          // 4096 float4
        int row = f >> 5;                 // 32 float4 per row
        int c4  = f & 31;
        float4 bv = *reinterpret_cast<const float4*>(&bias[d0 + c4 * 4]);
        const float* cp = &sC[row * X_BN + c4 * 4];
        float4 o;
        o.x = cp[0] + bv.x; o.y = cp[1] + bv.y; o.z = cp[2] + bv.z; o.w = cp[3] + bv.w;
        *reinterpret_cast<float4*>(
            &out[((size_t)((bbase + row) * TT + t)) * DD + d0 + c4 * 4]) = o;
    }
}

// ===========================================================================
// Kernel 2: persistent recurrence, fp16 operands, fp32 accum.
//   - 128 blocks x 512 threads; block tile = 32 batch x 64 d.
//   - Wh stripe (64 x 1024 fp16, 132 KB) resident in smem for all steps.
//   - FULL h tile (32 x 1024 fp16, 66 KB) per step via cp.async (2 halves).
//   - 16 warps = 2(N-half) x 8(K-slice); warp tile 32x32, K-slice 64 PER
//     HALF (total K=128/warp across both phases) -> ALL warps active in both
//     phases AND 1 mma per fragment load.
//   - 8 K-partials per N-half stored into the (then-dead) A region; epilogue
//     sums them (+preact), tanh, writes out fp32 + g_h fp16.
//   - 8 independent batch groups of 16 blocks; acq/rel barrier.
// ===========================================================================
#define RH_BM 32
#define RH_BN 64
#define RH_WLDH 1032                      // Wh ldm in halfs (1024+8)
#define RH_ALDH 1032                      // h  ldm in halfs (1024+8)
#define RH_GRPBLK 16                      // blocks per barrier group

#define RH_WH_BYTES (RH_BN * RH_WLDH * 2)             // 132096
#define RH_A_BYTES  (RH_BM * RH_ALDH * 2)             // 66048
#define RH_OFF_A  RH_WH_BYTES                         // 132096
#define RH_SMEM_BYTES (RH_OFF_A + RH_A_BYTES)         // 198144
// partial-C region overlays A (16 tiles of 32x32 fp32 = 65536 <= 66048)

__device__ __align__(256) unsigned g_cnt[8 * 64];
__device__ __align__(256) unsigned g_phase[8 * 64];   // monotonic across replays

__device__ __forceinline__ unsigned bar_arrive_acqrel(unsigned* p) {
    unsigned old;
    asm volatile("atom.acq_rel.gpu.add.u32 %0,[%1],1;"
                 : "=r"(old) : "l"(p) : "memory");
    return old;
}
__device__ __forceinline__ void bar_reset_relaxed(unsigned* p) {
    asm volatile("st.relaxed.gpu.u32 [%0],0;" :: "l"(p) : "memory");
}
__device__ __forceinline__ void bar_release(unsigned* p) {
    asm volatile("red.release.gpu.add.u32 [%0],1;" :: "l"(p) : "memory");
}
__device__ __forceinline__ unsigned bar_poll_acquire(const unsigned* p) {
    unsigned v;
    asm volatile("ld.acquire.gpu.u32 %0,[%1];" : "=r"(v) : "l"(p) : "memory");
    return v;
}
__device__ __forceinline__ void cp16(uint32_t saddr, const void* gptr) {
    asm volatile("cp.async.cg.shared.global [%0], [%1], 16;"
                 :: "r"(saddr), "l"(gptr));
}

__global__ void __launch_bounds__(512)
rnn_persistent(const float* __restrict__ W, float* __restrict__ out)
{
    extern __shared__ char smraw[];
    __half* sWh = (__half*)smraw;
    __half* sA  = (__half*)(smraw + RH_OFF_A);
    float*  sP  = (float*)(smraw + RH_OFF_A);   // partial-C overlay (post-mma)
    __shared__ unsigned s_base;

    const int tid = threadIdx.x;
    const int wid = tid >> 5;             // 16 warps = 2(N-half) x 8(K-slice)
    const int npos = wid & 1;             // N half: cols [npos*32, npos*32+32)
    const int kIdx = wid >> 1;            // K slice: 64 halfs per phase-half

    const int nT = blockIdx.x & 15;       // 16 d-stripes of 64
    const int mT = blockIdx.x >> 4;       // 8 batch groups of 32 (barrier scope)
    const int d0 = nT * RH_BN;
    const int b0 = mT * RH_BM;

    unsigned* cntp   = &g_cnt[mT * 64];
    unsigned* phasep = &g_phase[mT * 64];

    const uint32_t sA_u32 = (uint32_t)__cvta_generic_to_shared(sA);

    // --- Load Wh stripe once (fp32 -> fp16 RN): sWh[d][k], d = 0..63 ---
    {
        const float* Wh = W + DD;
        #pragma unroll
        for (int j = 0; j < 32; ++j) {
            int f   = tid + j * 512;
            int row = f >> 8;
            int c4  = f & 255;
            float4 v = *reinterpret_cast<const float4*>(
                &Wh[(size_t)(d0 + row) * WS + c4 * 4]);
            __half2* p = reinterpret_cast<__half2*>(&sWh[row * RH_WLDH + c4 * 4]);
            p[0] = __floats2half2_rn(v.x, v.y);
            p[1] = __floats2half2_rn(v.z, v.w);
        }
    }

    if (tid == 0) s_base = bar_poll_acquire(phasep);
    __syncthreads();
    const unsigned base = s_base;

    // full h tile: 32 rows x 1024 halfs; half h covers k [h*512, h*512+512)
    auto issue_half = [&](int h) {
        #pragma unroll
        for (int j = 0; j < 4; ++j) {
            int f   = tid + j * 512;      // 2048 segs: 32 rows x 64 segs
            int row = f >> 6;
            int sg  = (f & 63) + h * 64;
            const void* g = &g_h[(size_t)(b0 + row) * DD + sg * 8];
            uint32_t s = sA_u32 + (uint32_t)(row * RH_ALDH + sg * 8) * 2u;
            cp16(s, g);
        }
        asm volatile("cp.async.commit_group;");
    };

    // epilogue map: 32x64 floats = 512 float4, 1 per thread
    const int erow = tid >> 4;            // 16 float4 per row
    const int ec4  = tid & 15;
    const int enp  = ec4 >> 3;            // which N half
    const int ecc  = (ec4 & 7) * 4;       // col within 32-wide tile

    for (int t = 0; t < TT; ++t) {
        if (t == 0) {
            float* p = &out[((size_t)((b0 + erow) * TT + 0)) * DD + d0 + ec4 * 4];
            float4 v = __ldcg(reinterpret_cast<const float4*>(p));
            v.x = tanhf(v.x); v.y = tanhf(v.y); v.z = tanhf(v.z); v.w = tanhf(v.w);
            *reinterpret_cast<float4*>(p) = v;
            union { uint2 u; __half2 h2[2]; } pk;
            pk.h2[0] = __floats2half2_rn(v.x, v.y);
            pk.h2[1] = __floats2half2_rn(v.z, v.w);
            __stcg(reinterpret_cast<uint2*>(
                &g_h[(size_t)(b0 + erow) * DD + d0 + ec4 * 4]), pk.u);
        } else {
            issue_half(0);
            issue_half(1);

            float* eptr = &out[((size_t)((b0 + erow) * TT + t)) * DD + d0 + ec4 * 4];
            float4 pre = __ldcg(reinterpret_cast<const float4*>(eptr));

            wmma::fragment<wmma::accumulator, 16, 16, 16, float> acc[2][2];
            #pragma unroll
            for (int mf = 0; mf < 2; ++mf)
                #pragma unroll
                for (int nf = 0; nf < 2; ++nf)
                    wmma::fill_fragment(acc[mf][nf], 0.0f);

            // this warp's 64-wide K-slice within half ph: 4 k-steps of 16
            auto do_ksteps = [&](int ph) {
                const int kbase = ph * 512 + kIdx * 64;
                #pragma unroll
                for (int s = 0; s < 4; ++s) {
                    const int k = kbase + s * 16;
                    wmma::fragment<wmma::matrix_a, 16, 16, 16, __half, wmma::row_major> a[2];
                    wmma::fragment<wmma::matrix_b, 16, 16, 16, __half, wmma::col_major> b[2];
                    wmma::load_matrix_sync(a[0], &sA[k], RH_ALDH);
                    wmma::load_matrix_sync(a[1], &sA[16 * RH_ALDH + k], RH_ALDH);
                    wmma::load_matrix_sync(b[0], &sWh[(npos * 32) * RH_WLDH + k], RH_WLDH);
                    wmma::load_matrix_sync(b[1], &sWh[(npos * 32 + 16) * RH_WLDH + k], RH_WLDH);
                    #pragma unroll
                    for (int mf = 0; mf < 2; ++mf)
                        #pragma unroll
                        for (int nf = 0; nf < 2; ++nf)
                            wmma::mma_sync(acc[mf][nf], a[mf], b[nf], acc[mf][nf]);
                }
            };

            // half 0 ready -> ALL warps compute their slice of half 0
            asm volatile("cp.async.wait_group 1;");
            __syncthreads();
            do_ksteps(0);
            // half 1 ready -> ALL warps continue on half 1 (same accs)
            asm volatile("cp.async.wait_group 0;");
            __syncthreads();
            do_ksteps(1);
            __syncthreads();              // all mmas done; A region now dead

            // store this warp's 32x32 partial (K=128 slice total) into sP
            {
                float* tile = sP + (kIdx * 2 + npos) * 1024;
                wmma::store_matrix_sync(tile,                acc[0][0], 32, wmma::mem_row_major);
                wmma::store_matrix_sync(tile + 16,           acc[0][1], 32, wmma::mem_row_major);
                wmma::store_matrix_sync(tile + 16 * 32,      acc[1][0], 32, wmma::mem_row_major);
                wmma::store_matrix_sync(tile + 16 * 32 + 16, acc[1][1], 32, wmma::mem_row_major);
            }
            __syncthreads();

            // epilogue: sum 8 K-partials + preact -> tanh -> out + g_h
            {
                const int off = erow * 32 + ecc;
                float4 s0 = pre;
                #pragma unroll
                for (int kI = 0; kI < 8; ++kI) {
                    const float* pp = &sP[(kI * 2 + enp) * 1024 + off];
                    s0.x += pp[0]; s0.y += pp[1]; s0.z += pp[2]; s0.w += pp[3];
                }
                float4 o;
                o.x = tanhf(s0.x); o.y = tanhf(s0.y);
                o.z = tanhf(s0.z); o.w = tanhf(s0.w);
                *reinterpret_cast<float4*>(eptr) = o;
                union { uint2 u; __half2 h2[2]; } pk;
                pk.h2[0] = __floats2half2_rn(o.x, o.y);
                pk.h2[1] = __floats2half2_rn(o.z, o.w);
                __stcg(reinterpret_cast<uint2*>(
                    &g_h[(size_t)(b0 + erow) * DD + d0 + ec4 * 4]), pk.u);
            }
        }

        // group barrier (16 blocks sharing this batch group), skip after last
        if (t != TT - 1) {
            __syncthreads();
            if (tid == 0) {
                unsigned old = bar_arrive_acqrel(cntp);
                if (old == RH_GRPBLK - 1) {
                    bar_reset_relaxed(cntp);
                    bar_release(phasep);
                } else {
                    const unsigned target = base + (unsigned)(t + 1);
                    while ((int)(bar_poll_acquire(phasep) - target) < 0) { }
                }
            }
            __syncthreads();
        }
    }
}

// ===========================================================================
// Launch
// ===========================================================================
extern "C" void kernel_launch(void* const* d_in, const int* in_sizes, int n_in,
                              void* d_out, int out_size)
{
    const float* x    = (const float*)d_in[0];
    const float* W    = (const float*)d_in[1];
    const float* bias = (const float*)d_in[2];
    float* out = (float*)d_out;

    cudaFuncSetAttribute(gemm_x_f16, cudaFuncAttributeMaxDynamicSharedMemorySize,
                         X_SMEM_BYTES);
    cudaFuncSetAttribute(rnn_persistent, cudaFuncAttributeMaxDynamicSharedMemorySize,
                         RH_SMEM_BYTES);

    dim3 g1(DD / X_BN, (TT * BB) / X_BM);   // (8, 512)
    gemm_x_f16<<<g1, 256, X_SMEM_BYTES>>>(x, W, bias, out);

    rnn_persistent<<<128, 512, RH_SMEM_BYTES>>>(W, out);
}